// round 11
// baseline (speedup 1.0000x reference)
#include <cuda_runtime.h>
#include <cstdint>

// x: (8, 16, 4096, 128) fp32 -> out[b,h,s,d] = cos(s * 10000^(-(d>>1)/64)) * x
// Diagonal of R recomputed in-flight (rel_err ~2e-5 proven in R10).
#define SEQ     4096
#define DK      128
#define INNER4  (SEQ * DK / 4)        // 131072 float4s per (b,h) slice
#define NTOT4   (8 * 16 * INNER4)     // 16777216 float4s
#define TPB     256
#define UN      4                     // float4s per chunk per thread
#define ITERS   8                     // chunks per block (128KB contiguous)
#define CHUNK   (TPB * UN)            // 1024 float4s = 16KB

// ---- accurate 2^(-k * log2(10000)/64), flag-proof (no libdevice calls) ----
__device__ __forceinline__ float freq_acc(int k) {
    const float C_hi = (float)0.20762050593045951;
    const float C_lo = (float)(0.20762050593045951 - (double)(float)0.20762050593045951);
    float kf = (float)k;
    float p  = kf * C_hi;
    float pe = fmaf(kf, C_hi, -p);          // exact two-prod residual
    float plo = fmaf(kf, C_lo, pe);
    float ehi = -p, elo = -plo;
    float i = rintf(ehi);
    float f = (ehi - i) + elo;              // |f| <= ~0.5
    float r = 1.52527338040598e-5f;
    r = fmaf(r, f, 1.54035303933816e-4f);
    r = fmaf(r, f, 0.00133335581464284f);
    r = fmaf(r, f, 0.00961812910762848f);
    r = fmaf(r, f, 0.0555041086648216f);
    r = fmaf(r, f, 0.240226506959101f);
    r = fmaf(r, f, 0.693147180559945f);
    r = fmaf(r, f, 1.0f);
    float scale = __int_as_float(((int)i + 127) << 23);
    return r * scale;
}

// ---- accurate cos for x in [0, ~2600*pi/2), Cody-Waite + cephes ----
__device__ __forceinline__ float cos_acc(float x) {
    const float TWO_OVER_PI = 0.63661977236758134f;
    const float E1 = 1.5703125f;
    const float E2 = 4.837512969970703125e-4f;
    const float E3 = 7.54978995489188216e-8f;
    float nf = rintf(x * TWO_OVER_PI);
    int   n  = (int)nf;
    float rr = fmaf(-nf, E1, x);
    rr = fmaf(-nf, E2, rr);
    rr = fmaf(-nf, E3, rr);
    float z = rr * rr;
    float pc = fmaf(z, 2.443315711809948e-5f, -1.388731625493765e-3f);
    pc = fmaf(z, pc, 4.166664568298827e-2f);
    pc = fmaf(z * z, pc, fmaf(z, -0.5f, 1.0f));
    float ps = fmaf(z, -1.9515295891e-4f, 8.3321608736e-3f);
    ps = fmaf(z, ps, -1.6666654611e-1f);
    ps = fmaf(z * ps, rr, rr);
    int m = n & 3;
    float mag = (m & 1) ? ps : pc;
    return ((m == 1) | (m == 2)) ? -mag : mag;
}

// Double-buffered streaming kernel: each block owns 128KB contiguous; the next
// chunk's loads are issued BEFORE the current chunk's stores, so read traffic
// stays in flight through every store phase (fights R/W turnaround).
__global__ void __launch_bounds__(TPB) rope_pipe_kernel(
    const float4* __restrict__ x4, float4* __restrict__ out4) {

    int tid = threadIdx.x;
    size_t base = (size_t)blockIdx.x * (CHUNK * ITERS) + tid;
    int d4 = tid & 31;                           // constant: stride-256 sites
    int s0 = (int)((base >> 5) & (SEQ - 1));     // block spans 256 s-rows, 1 slice

    float f0 = freq_acc(2 * d4);
    float f1 = freq_acc(2 * d4 + 1);

    float4 buf[2][UN];

    // Prologue: load chunk 0
    #pragma unroll
    for (int u = 0; u < UN; u++)
        buf[0][u] = __ldcs(&x4[base + (size_t)u * TPB]);

    #pragma unroll
    for (int it = 0; it < ITERS; it++) {
        const int cur = it & 1, nxt = cur ^ 1;

        // Issue next chunk's loads first (stay in flight during stores below)
        if (it + 1 < ITERS) {
            #pragma unroll
            for (int u = 0; u < UN; u++)
                buf[nxt][u] = __ldcs(&x4[base + (size_t)(it + 1) * CHUNK
                                              + (size_t)u * TPB]);
        }

        // Compute + store current chunk
        #pragma unroll
        for (int u = 0; u < UN; u++) {
            float sf = (float)(s0 + it * 32 + u * 8);
            float c0 = cos_acc(__fmul_rn(sf, f0));
            float c1 = cos_acc(__fmul_rn(sf, f1));
            float4 xv = buf[cur][u];
            float4 ov;
            ov.x = xv.x * c0;
            ov.y = xv.y * c0;
            ov.z = xv.z * c1;
            ov.w = xv.w * c1;
            __stcs(&out4[base + (size_t)it * CHUNK + (size_t)u * TPB], ov);
        }
    }
}

extern "C" void kernel_launch(void* const* d_in, const int* in_sizes, int n_in,
                              void* d_out, int out_size) {
    const float* x = (const float*)d_in[0];
    // d_in[1] = token_positions (unused, as in the reference)
    // d_in[2] = R (unused: diagonal recomputed in-flight)
    float* out = (float*)d_out;

    rope_pipe_kernel<<<NTOT4 / (CHUNK * ITERS), TPB>>>(
        (const float4*)x, (float4*)out);
}